// round 3
// baseline (speedup 1.0000x reference)
#include <cuda_runtime.h>
#include <cstdint>

#define T_STEPS 2048
#define BATCH   32
#define INDIM   512
#define HID     512
#define G4      2048   // 4*HID

typedef unsigned long long u64;

// packed f32x2 helpers (sm_103a packed fp32 pipe: 2x FFMA throughput)
__device__ __forceinline__ u64 pk2(float x) {
    u64 r; asm("mov.b64 %0, {%1, %1};" : "=l"(r) : "f"(x)); return r;
}
__device__ __forceinline__ void ffma2(u64& d, u64 a, u64 b, u64 c) {
    asm("fma.rn.f32x2 %0, %1, %2, %3;" : "=l"(d) : "l"(a), "l"(b), "l"(c));
}
__device__ __forceinline__ void fadd2(u64& d, u64 a, u64 b) {
    asm("add.rn.f32x2 %0, %1, %2;" : "=l"(d) : "l"(a), "l"(b));
}
__device__ __forceinline__ float2 up2(u64 v) {
    float2 f; asm("mov.b64 {%0, %1}, %2;" : "=f"(f.x), "=f"(f.y) : "l"(v)); return f;
}
__device__ __forceinline__ float tanhfast(float x) {
    float r; asm("tanh.approx.f32 %0, %1;" : "=f"(r) : "f"(x)); return r;
}
__device__ __forceinline__ float sigfast(float x) {
    return fmaf(tanhfast(0.5f * x), 0.5f, 0.5f);
}

// -------- persistent device scratch --------
__device__ float    g_xp[(size_t)T_STEPS * BATCH * G4];   // x_proj[t][b][g]
__device__ float    g_hT[2][HID * BATCH];                 // h transposed: [k][b], double buffered
__device__ unsigned g_flag[2][64];                        // per-(bgroup, jgroup) epoch flags

// ============================================================================
// Kernel A: x_proj = seq @ W_ih^T + (b_ih + b_hh)     (unchanged from R2)
// ============================================================================
__global__ __launch_bounds__(256) void xproj_kernel(
    const float* __restrict__ seq,
    const float* __restrict__ Wih,
    const float* __restrict__ bih,
    const float* __restrict__ bhh)
{
    __shared__ float As[32 * 128];   // [k][m], word = k*128 + (m ^ (((k>>2)&7)<<2))
    __shared__ float Bs[32 * 64];    // [k][n], word = k*64  + (n ^ (((k>>2)&7)<<2))

    const int tid = threadIdx.x;
    const int m0g = blockIdx.y * 128;
    const int n0g = blockIdx.x * 64;
    const int tx  = tid & 15;        // n: tx*4
    const int ty  = tid >> 4;        // m: ty*8

    u64 acc[4][4];
    #pragma unroll
    for (int i = 0; i < 4; ++i)
        #pragma unroll
        for (int j = 0; j < 4; ++j) acc[i][j] = 0ull;

    for (int kb = 0; kb < 512; kb += 32) {
        #pragma unroll
        for (int i = 0; i < 4; ++i) {
            int flat = tid + i * 256;
            int kq = flat & 7;
            int m  = flat >> 3;
            float4 v = *(const float4*)(seq + (size_t)(m0g + m) * 512 + kb + kq * 4);
            int base = (kq * 4) * 128 + (m ^ (kq << 2));
            As[base      ] = v.x;
            As[base + 128] = v.y;
            As[base + 256] = v.z;
            As[base + 384] = v.w;
        }
        #pragma unroll
        for (int i = 0; i < 2; ++i) {
            int flat = tid + i * 256;
            int kq = flat & 7;
            int n  = flat >> 3;
            float4 v = *(const float4*)(Wih + (size_t)(n0g + n) * 512 + kb + kq * 4);
            int base = (kq * 4) * 64 + (n ^ (kq << 2));
            Bs[base      ] = v.x;
            Bs[base + 64 ] = v.y;
            Bs[base + 128] = v.z;
            Bs[base + 192] = v.w;
        }
        __syncthreads();

        #pragma unroll
        for (int kk = 0; kk < 32; ++kk) {
            const int c = ((kk >> 2) & 7) << 2;
            ulonglong2 A0 = *(const ulonglong2*)(As + kk * 128 + ((ty * 8    ) ^ c));
            ulonglong2 A1 = *(const ulonglong2*)(As + kk * 128 + ((ty * 8 + 4) ^ c));
            float4 bv     = *(const float4*)    (Bs + kk * 64  + ((tx * 4    ) ^ c));
            u64 b0 = pk2(bv.x), b1 = pk2(bv.y), b2 = pk2(bv.z), b3 = pk2(bv.w);
            ffma2(acc[0][0], A0.x, b0, acc[0][0]);
            ffma2(acc[0][1], A0.x, b1, acc[0][1]);
            ffma2(acc[0][2], A0.x, b2, acc[0][2]);
            ffma2(acc[0][3], A0.x, b3, acc[0][3]);
            ffma2(acc[1][0], A0.y, b0, acc[1][0]);
            ffma2(acc[1][1], A0.y, b1, acc[1][1]);
            ffma2(acc[1][2], A0.y, b2, acc[1][2]);
            ffma2(acc[1][3], A0.y, b3, acc[1][3]);
            ffma2(acc[2][0], A1.x, b0, acc[2][0]);
            ffma2(acc[2][1], A1.x, b1, acc[2][1]);
            ffma2(acc[2][2], A1.x, b2, acc[2][2]);
            ffma2(acc[2][3], A1.x, b3, acc[2][3]);
            ffma2(acc[3][0], A1.y, b0, acc[3][0]);
            ffma2(acc[3][1], A1.y, b1, acc[3][1]);
            ffma2(acc[3][2], A1.y, b2, acc[3][2]);
            ffma2(acc[3][3], A1.y, b3, acc[3][3]);
        }
        __syncthreads();
    }

    float bs[4];
    #pragma unroll
    for (int j = 0; j < 4; ++j)
        bs[j] = bih[n0g + tx * 4 + j] + bhh[n0g + tx * 4 + j];

    #pragma unroll
    for (int mp = 0; mp < 4; ++mp) {
        float2 p0 = up2(acc[mp][0]);
        float2 p1 = up2(acc[mp][1]);
        float2 p2 = up2(acc[mp][2]);
        float2 p3 = up2(acc[mp][3]);
        float4 r0 = make_float4(p0.x + bs[0], p1.x + bs[1], p2.x + bs[2], p3.x + bs[3]);
        float4 r1 = make_float4(p0.y + bs[0], p1.y + bs[1], p2.y + bs[2], p3.y + bs[3]);
        size_t row0 = (size_t)(m0g + ty * 8 + 2 * mp) * 2048 + n0g + tx * 4;
        __stcs((float4*)(g_xp + row0), r0);
        __stcs((float4*)(g_xp + row0 + 2048), r1);
    }
}

// ============================================================================
__global__ void reset_kernel() {
    int i = threadIdx.x;
    if (i < 64) { g_flag[0][i] = 0u; g_flag[1][i] = 0u; }
}

// ============================================================================
// Kernel B: persistent recurrence. 128 CTAs x 256 threads, f32x2 math.
//   Barrier: per-CTA epoch flags, split into 2 independent batch-groups of
//   64 CTAs (batch halves never interact). Warp 0 polls all 64 flags in
//   parallel — no atomic serialization.
// ============================================================================
__global__ __launch_bounds__(256) void lstm_rec_kernel(
    const float* __restrict__ h0,
    const float* __restrict__ c0,
    const float* __restrict__ Whh,
    float* __restrict__ out,
    long long out_size)
{
    extern __shared__ float sm[];
    float* Ws  = sm;                           // 512*32: [k][r], r^(((k>>5)&1)<<2)
    float* Hs  = Ws + 512 * 32;                // 512*32: [k][b], b^(((k>>5)&1)<<4)
    u64*   Red = (u64*)(Hs + 512 * 32);        // 16 groups * 16 r-pairs * 17
    float* Gs  = (float*)(Red + 16 * 16 * 17); // 512: gates [r*16+b]
    float* Cs  = Gs + 512;                     // 128: c slice [b*8+j]

    const int tid = threadIdx.x;
    const int ct  = blockIdx.x;
    const int jg  = ct >> 1;                   // j-group index [0,64)
    const int bg  = ct & 1;                    // batch-group [0,2)
    const int jb  = jg * 8;
    const int bb  = bg * 16;

    // ---- one-time: W_hh rows -> K-major swizzled SMEM ----
    for (int idx = tid; idx < 32 * 512; idx += 256) {
        int r = idx & 31, k = idx >> 5;
        int q = r >> 3, j = r & 7;
        float w = Whh[(size_t)(q * 512 + jb + j) * 512 + k];
        Ws[k * 32 + (r ^ (((k >> 5) & 1) << 2))] = w;
    }
    const int jj  = tid & 7;
    const int bbt = tid >> 3;
    if (tid < 128) Cs[bbt * 8 + jj] = c0[(bb + bbt) * 512 + jb + jj];
    for (int idx = tid; idx < 512 * 16; idx += 256) {
        int b = idx & 15, k = idx >> 4;
        Hs[k * 32 + (b ^ (((k >> 5) & 1) << 4))] = h0[(bb + b) * 512 + k];
    }
    __syncthreads();

    const int gid = tid >> 4;          // K-group: k in [gid*32, gid*32+32)
    const int l16 = tid & 15;
    const int tm  = l16 & 3;           // r0 = tm*8
    const int tn  = l16 >> 2;          // b0 = tn*4
    const int cA  = (gid & 1) << 2;
    const int cH  = (gid & 1) << 4;
    const float* wsp = Ws + (size_t)gid * 32 * 32;
    const float* hsp = Hs + (size_t)gid * 32 * 32;
    const int aw0 = (tm * 8    ) ^ cA;
    const int aw1 = (tm * 8 + 4) ^ cA;
    const int hw  = (tn * 4    ) ^ cH;

    for (int t = 0; t < T_STEPS; ++t) {
        // prefetch x_proj gate values (DRAM latency hidden behind GEMM)
        float xq0 = 0.f, xq1 = 0.f, xq2 = 0.f, xq3 = 0.f;
        if (tid < 128) {
            size_t base = ((size_t)t * 32 + bb + bbt) * 2048 + jb + jj;
            xq0 = __ldcs(&g_xp[base]);
            xq1 = __ldcs(&g_xp[base + 512]);
            xq2 = __ldcs(&g_xp[base + 1024]);
            xq3 = __ldcs(&g_xp[base + 1536]);
        }

        if (t > 0) {
            const float* hsrc = g_hT[t & 1];
            #pragma unroll
            for (int i = 0; i < 8; ++i) {
                int flat = tid + i * 256;
                int q  = flat & 3;
                int kr = flat >> 2;
                float4 v = __ldcg((const float4*)(hsrc + kr * 32 + bb + q * 4));
                *(float4*)(Hs + kr * 32 + ((q * 4) ^ (((kr >> 5) & 1) << 4))) = v;
            }
            __syncthreads();
        }

        // ---- per-group GEMM: 8r x 4b tile over 32 k ----
        u64 acc[4][4];
        #pragma unroll
        for (int i = 0; i < 4; ++i)
            #pragma unroll
            for (int j = 0; j < 4; ++j) acc[i][j] = 0ull;

        #pragma unroll 8
        for (int k = 0; k < 32; ++k) {
            ulonglong2 A0 = *(const ulonglong2*)(wsp + k * 32 + aw0);
            ulonglong2 A1 = *(const ulonglong2*)(wsp + k * 32 + aw1);
            float4 bv     = *(const float4*)    (hsp + k * 32 + hw);
            u64 b0 = pk2(bv.x), b1 = pk2(bv.y), b2 = pk2(bv.z), b3 = pk2(bv.w);
            ffma2(acc[0][0], A0.x, b0, acc[0][0]);
            ffma2(acc[0][1], A0.x, b1, acc[0][1]);
            ffma2(acc[0][2], A0.x, b2, acc[0][2]);
            ffma2(acc[0][3], A0.x, b3, acc[0][3]);
            ffma2(acc[1][0], A0.y, b0, acc[1][0]);
            ffma2(acc[1][1], A0.y, b1, acc[1][1]);
            ffma2(acc[1][2], A0.y, b2, acc[1][2]);
            ffma2(acc[1][3], A0.y, b3, acc[1][3]);
            ffma2(acc[2][0], A1.x, b0, acc[2][0]);
            ffma2(acc[2][1], A1.x, b1, acc[2][1]);
            ffma2(acc[2][2], A1.x, b2, acc[2][2]);
            ffma2(acc[2][3], A1.x, b3, acc[2][3]);
            ffma2(acc[3][0], A1.y, b0, acc[3][0]);
            ffma2(acc[3][1], A1.y, b1, acc[3][1]);
            ffma2(acc[3][2], A1.y, b2, acc[3][2]);
            ffma2(acc[3][3], A1.y, b3, acc[3][3]);
        }

        #pragma unroll
        for (int mp = 0; mp < 4; ++mp)
            #pragma unroll
            for (int n = 0; n < 4; ++n)
                Red[(gid * 16 + tm * 4 + mp) * 17 + (tn * 4 + n)] = acc[mp][n];
        __syncthreads();

        // ---- reduce 16 groups ----
        {
            int rp = tid >> 4, b = tid & 15;
            u64 s = Red[rp * 17 + b];
            #pragma unroll
            for (int g = 1; g < 16; ++g)
                fadd2(s, s, Red[(g * 16 + rp) * 17 + b]);
            float2 f = up2(s);
            Gs[(rp * 2    ) * 16 + b] = f.x;
            Gs[(rp * 2 + 1) * 16 + b] = f.y;
        }
        __syncthreads();

        // ---- LSTM cell update ----
        if (tid < 128) {
            const int j = jj, b = bbt;
            float zi = xq0 + Gs[(     j) * 16 + b];
            float zf = xq1 + Gs[( 8 + j) * 16 + b];
            float zg = xq2 + Gs[(16 + j) * 16 + b];
            float zo = xq3 + Gs[(24 + j) * 16 + b];
            float ig = sigfast(zi);
            float fg = sigfast(zf);
            float gg = tanhfast(zg);
            float og = sigfast(zo);
            float cn = fg * Cs[b * 8 + j] + ig * gg;
            Cs[b * 8 + j] = cn;
            float hn = og * tanhfast(cn);

            g_hT[(t + 1) & 1][(jb + j) * 32 + bb + b] = hn;
            out[((size_t)t * 32 + bb + b) * 512 + jb + j] = hn;

            if (t == T_STEPS - 1) {
                long long need = (long long)T_STEPS * BATCH * HID + 2LL * BATCH * HID;
                if (out_size >= need) {
                    size_t ob = (size_t)T_STEPS * BATCH * HID;
                    out[ob + (bb + b) * 512 + jb + j]               = hn;  // h_f
                    out[ob + BATCH * HID + (bb + b) * 512 + jb + j] = cn;  // c_f
                }
            }
        }

        // ---- flag-array barrier over this batch-group's 64 CTAs ----
        if (t < T_STEPS - 1) {
            __syncthreads();                    // all h stores issued, CTA-visible
            if (tid == 0) {
                __threadfence();                // release: h visible at gpu scope
                ((volatile unsigned*)g_flag[bg])[jg] = (unsigned)(t + 1);
            }
            if (tid < 32) {
                const unsigned tgt = (unsigned)(t + 1);
                const volatile unsigned* f = (const volatile unsigned*)g_flag[bg];
                while (true) {
                    unsigned v0 = f[tid];
                    unsigned v1 = f[tid + 32];
                    if (__all_sync(0xffffffffu, (v0 >= tgt) & (v1 >= tgt))) break;
                }
                __threadfence();                // acquire side
            }
            __syncthreads();
        }
    }
}

// ============================================================================
extern "C" void kernel_launch(void* const* d_in, const int* in_sizes, int n_in,
                              void* d_out, int out_size)
{
    const float* seq = (const float*)d_in[0];
    const float* h0  = (const float*)d_in[1];
    const float* c0  = (const float*)d_in[2];
    const float* Wih = (const float*)d_in[3];
    const float* Whh = (const float*)d_in[4];
    const float* bih = (const float*)d_in[5];
    const float* bhh = (const float*)d_in[6];
    float* out = (float*)d_out;
    (void)in_sizes; (void)n_in;

    dim3 gA(2048 / 64, (T_STEPS * BATCH) / 128);   // (32, 512)
    xproj_kernel<<<gA, 256>>>(seq, Wih, bih, bhh);

    reset_kernel<<<1, 64>>>();

    size_t smem = (size_t)(512 * 32 + 512 * 32 + 512) * sizeof(float)
                + (size_t)(16 * 16 * 17) * sizeof(u64)
                + (size_t)128 * sizeof(float);
    cudaFuncSetAttribute(lstm_rec_kernel,
                         cudaFuncAttributeMaxDynamicSharedMemorySize, (int)smem);
    lstm_rec_kernel<<<128, 256, smem>>>(h0, c0, Whh, out, (long long)out_size);
}

// round 4
// speedup vs baseline: 1.8775x; 1.8775x over previous
#include <cuda_runtime.h>
#include <cstdint>

#define T_STEPS 2048
#define BATCH   32
#define INDIM   512
#define HID     512
#define G4      2048   // 4*HID

typedef unsigned long long u64;

// packed f32x2 helpers (sm_103a packed fp32 pipe: 2x FFMA throughput)
__device__ __forceinline__ u64 pk2(float x) {
    u64 r; asm("mov.b64 %0, {%1, %1};" : "=l"(r) : "f"(x)); return r;
}
__device__ __forceinline__ void ffma2(u64& d, u64 a, u64 b, u64 c) {
    asm("fma.rn.f32x2 %0, %1, %2, %3;" : "=l"(d) : "l"(a), "l"(b), "l"(c));
}
__device__ __forceinline__ void fadd2(u64& d, u64 a, u64 b) {
    asm("add.rn.f32x2 %0, %1, %2;" : "=l"(d) : "l"(a), "l"(b));
}
__device__ __forceinline__ float2 up2(u64 v) {
    float2 f; asm("mov.b64 {%0, %1}, %2;" : "=f"(f.x), "=f"(f.y) : "l"(v)); return f;
}
__device__ __forceinline__ float tanhfast(float x) {
    float r; asm("tanh.approx.f32 %0, %1;" : "=f"(r) : "f"(x)); return r;
}
__device__ __forceinline__ float sigfast(float x) {
    return fmaf(tanhfast(0.5f * x), 0.5f, 0.5f);
}

// -------- persistent device scratch --------
__device__ float    g_xp[(size_t)T_STEPS * BATCH * G4];   // x_proj[t][b][g]
__device__ float    g_hT[2][HID * BATCH];                 // h transposed: [k][b], double buffered
__device__ unsigned g_bar2[2][32];                        // per-batch-group barrier counters (padded)

// ============================================================================
// Kernel A: x_proj = seq @ W_ih^T + (b_ih + b_hh)
//   128M x 64N x 32K tiles, 256 threads, 8x4 per-thread f32x2 tile.
//   Double-buffered SMEM pipeline: LDG(next) -> compute(cur) -> STS(next).
// ============================================================================
__global__ __launch_bounds__(256) void xproj_kernel(
    const float* __restrict__ seq,
    const float* __restrict__ Wih,
    const float* __restrict__ bih,
    const float* __restrict__ bhh)
{
    extern __shared__ float smA[];
    float* As = smA;            // 2 x 4096 floats: [k][m], m ^ (((k>>2)&7)<<2)
    float* Bs = smA + 8192;     // 2 x 2048 floats: [k][n], n ^ (((k>>2)&7)<<2)

    const int tid = threadIdx.x;
    const int m0g = blockIdx.y * 128;
    const int n0g = blockIdx.x * 64;
    const int tx  = tid & 15;        // n: tx*4
    const int ty  = tid >> 4;        // m: ty*8

    // precompute load/store addressing (kb-independent)
    int baseA[4]; const float* gA[4];
    #pragma unroll
    for (int i = 0; i < 4; ++i) {
        int flat = tid + i * 256;            // [0,1024)
        int kq = flat & 7;
        int m  = flat >> 3;
        baseA[i] = (kq * 4) * 128 + (m ^ (kq << 2));
        gA[i] = seq + (size_t)(m0g + m) * 512 + kq * 4;
    }
    int baseB[2]; const float* gB[2];
    #pragma unroll
    for (int i = 0; i < 2; ++i) {
        int flat = tid + i * 256;            // [0,512)
        int kq = flat & 7;
        int n  = flat >> 3;
        baseB[i] = (kq * 4) * 64 + (n ^ (kq << 2));
        gB[i] = Wih + (size_t)(n0g + n) * 512 + kq * 4;
    }

    u64 acc[4][4];
    #pragma unroll
    for (int i = 0; i < 4; ++i)
        #pragma unroll
        for (int j = 0; j < 4; ++j) acc[i][j] = 0ull;

    // ---- prologue: tile kb=0 into buffer 0 ----
    #pragma unroll
    for (int i = 0; i < 4; ++i) {
        float4 v = *(const float4*)(gA[i]);
        As[baseA[i]      ] = v.x;
        As[baseA[i] + 128] = v.y;
        As[baseA[i] + 256] = v.z;
        As[baseA[i] + 384] = v.w;
    }
    #pragma unroll
    for (int i = 0; i < 2; ++i) {
        float4 v = *(const float4*)(gB[i]);
        Bs[baseB[i]      ] = v.x;
        Bs[baseB[i] + 64 ] = v.y;
        Bs[baseB[i] + 128] = v.z;
        Bs[baseB[i] + 192] = v.w;
    }
    __syncthreads();

    for (int it = 0; it < 16; ++it) {
        const int p = it & 1;
        float4 a4[4], b4[2];
        if (it < 15) {
            const int kb = (it + 1) * 32;
            #pragma unroll
            for (int i = 0; i < 4; ++i) a4[i] = *(const float4*)(gA[i] + kb);
            #pragma unroll
            for (int i = 0; i < 2; ++i) b4[i] = *(const float4*)(gB[i] + kb);
        }

        const float* Ap = As + p * 4096;
        const float* Bp = Bs + p * 2048;
        #pragma unroll
        for (int kk = 0; kk < 32; ++kk) {
            const int c = ((kk >> 2) & 7) << 2;
            ulonglong2 A0 = *(const ulonglong2*)(Ap + kk * 128 + ((ty * 8    ) ^ c));
            ulonglong2 A1 = *(const ulonglong2*)(Ap + kk * 128 + ((ty * 8 + 4) ^ c));
            float4 bv     = *(const float4*)    (Bp + kk * 64  + ((tx * 4    ) ^ c));
            u64 b0 = pk2(bv.x), b1 = pk2(bv.y), b2 = pk2(bv.z), b3 = pk2(bv.w);
            ffma2(acc[0][0], A0.x, b0, acc[0][0]);
            ffma2(acc[0][1], A0.x, b1, acc[0][1]);
            ffma2(acc[0][2], A0.x, b2, acc[0][2]);
            ffma2(acc[0][3], A0.x, b3, acc[0][3]);
            ffma2(acc[1][0], A0.y, b0, acc[1][0]);
            ffma2(acc[1][1], A0.y, b1, acc[1][1]);
            ffma2(acc[1][2], A0.y, b2, acc[1][2]);
            ffma2(acc[1][3], A0.y, b3, acc[1][3]);
            ffma2(acc[2][0], A1.x, b0, acc[2][0]);
            ffma2(acc[2][1], A1.x, b1, acc[2][1]);
            ffma2(acc[2][2], A1.x, b2, acc[2][2]);
            ffma2(acc[2][3], A1.x, b3, acc[2][3]);
            ffma2(acc[3][0], A1.y, b0, acc[3][0]);
            ffma2(acc[3][1], A1.y, b1, acc[3][1]);
            ffma2(acc[3][2], A1.y, b2, acc[3][2]);
            ffma2(acc[3][3], A1.y, b3, acc[3][3]);
        }

        if (it < 15) {
            float* Aw = As + (p ^ 1) * 4096;
            float* Bw = Bs + (p ^ 1) * 2048;
            #pragma unroll
            for (int i = 0; i < 4; ++i) {
                Aw[baseA[i]      ] = a4[i].x;
                Aw[baseA[i] + 128] = a4[i].y;
                Aw[baseA[i] + 256] = a4[i].z;
                Aw[baseA[i] + 384] = a4[i].w;
            }
            #pragma unroll
            for (int i = 0; i < 2; ++i) {
                Bw[baseB[i]      ] = b4[i].x;
                Bw[baseB[i] + 64 ] = b4[i].y;
                Bw[baseB[i] + 128] = b4[i].z;
                Bw[baseB[i] + 192] = b4[i].w;
            }
        }
        __syncthreads();
    }

    float bs[4];
    #pragma unroll
    for (int j = 0; j < 4; ++j)
        bs[j] = bih[n0g + tx * 4 + j] + bhh[n0g + tx * 4 + j];

    #pragma unroll
    for (int mp = 0; mp < 4; ++mp) {
        float2 p0 = up2(acc[mp][0]);
        float2 p1 = up2(acc[mp][1]);
        float2 p2 = up2(acc[mp][2]);
        float2 p3 = up2(acc[mp][3]);
        float4 r0 = make_float4(p0.x + bs[0], p1.x + bs[1], p2.x + bs[2], p3.x + bs[3]);
        float4 r1 = make_float4(p0.y + bs[0], p1.y + bs[1], p2.y + bs[2], p3.y + bs[3]);
        size_t row0 = (size_t)(m0g + ty * 8 + 2 * mp) * 2048 + n0g + tx * 4;
        __stcs((float4*)(g_xp + row0), r0);
        __stcs((float4*)(g_xp + row0 + 2048), r1);
    }
}

// ============================================================================
__global__ void reset_kernel() {
    if (threadIdx.x < 2) g_bar2[threadIdx.x][0] = 0u;
}

// ============================================================================
// Kernel B: persistent recurrence. 128 CTAs x 256 threads, f32x2 math.
//   Barrier: R2-style single hot counter (atomicAdd arrival, one poller per
//   CTA), one counter per independent batch-group (64 arrivals each).
// ============================================================================
__global__ __launch_bounds__(256) void lstm_rec_kernel(
    const float* __restrict__ h0,
    const float* __restrict__ c0,
    const float* __restrict__ Whh,
    float* __restrict__ out,
    long long out_size)
{
    extern __shared__ float sm[];
    float* Ws  = sm;                           // 512*32: [k][r], r^(((k>>5)&1)<<2)
    float* Hs  = Ws + 512 * 32;                // 512*32: [k][b], b^(((k>>5)&1)<<4)
    u64*   Red = (u64*)(Hs + 512 * 32);        // 16 groups * 16 r-pairs * 17
    float* Gs  = (float*)(Red + 16 * 16 * 17); // 512: gates [r*16+b]
    float* Cs  = Gs + 512;                     // 128: c slice [b*8+j]

    const int tid = threadIdx.x;
    const int ct  = blockIdx.x;
    const int jg  = ct >> 1;                   // j-group [0,64)
    const int bg  = ct & 1;                    // batch-group [0,2)
    const int jb  = jg * 8;
    const int bb  = bg * 16;

    // ---- one-time: W_hh rows -> K-major swizzled SMEM ----
    for (int idx = tid; idx < 32 * 512; idx += 256) {
        int r = idx & 31, k = idx >> 5;
        int q = r >> 3, j = r & 7;
        float w = Whh[(size_t)(q * 512 + jb + j) * 512 + k];
        Ws[k * 32 + (r ^ (((k >> 5) & 1) << 2))] = w;
    }
    const int jj  = tid & 7;
    const int bbt = tid >> 3;
    if (tid < 128) Cs[bbt * 8 + jj] = c0[(bb + bbt) * 512 + jb + jj];
    for (int idx = tid; idx < 512 * 16; idx += 256) {
        int b = idx & 15, k = idx >> 4;
        Hs[k * 32 + (b ^ (((k >> 5) & 1) << 4))] = h0[(bb + b) * 512 + k];
    }
    __syncthreads();

    const int gid = tid >> 4;          // K-group: k in [gid*32, gid*32+32)
    const int l16 = tid & 15;
    const int tm  = l16 & 3;           // r0 = tm*8
    const int tn  = l16 >> 2;          // b0 = tn*4
    const int cA  = (gid & 1) << 2;
    const int cH  = (gid & 1) << 4;
    const float* wsp = Ws + (size_t)gid * 32 * 32;
    const float* hsp = Hs + (size_t)gid * 32 * 32;
    const int aw0 = (tm * 8    ) ^ cA;
    const int aw1 = (tm * 8 + 4) ^ cA;
    const int hw  = (tn * 4    ) ^ cH;

    for (int t = 0; t < T_STEPS; ++t) {
        // prefetch x_proj gate values (DRAM latency hidden behind GEMM)
        float xq0 = 0.f, xq1 = 0.f, xq2 = 0.f, xq3 = 0.f;
        if (tid < 128) {
            size_t base = ((size_t)t * 32 + bb + bbt) * 2048 + jb + jj;
            xq0 = __ldcs(&g_xp[base]);
            xq1 = __ldcs(&g_xp[base + 512]);
            xq2 = __ldcs(&g_xp[base + 1024]);
            xq3 = __ldcs(&g_xp[base + 1536]);
        }

        if (t > 0) {
            const float* hsrc = g_hT[t & 1];
            #pragma unroll
            for (int i = 0; i < 8; ++i) {
                int flat = tid + i * 256;
                int q  = flat & 3;
                int kr = flat >> 2;
                float4 v = __ldcg((const float4*)(hsrc + kr * 32 + bb + q * 4));
                *(float4*)(Hs + kr * 32 + ((q * 4) ^ (((kr >> 5) & 1) << 4))) = v;
            }
            __syncthreads();
        }

        // ---- per-group GEMM: 8r x 4b tile over 32 k ----
        u64 acc[4][4];
        #pragma unroll
        for (int i = 0; i < 4; ++i)
            #pragma unroll
            for (int j = 0; j < 4; ++j) acc[i][j] = 0ull;

        #pragma unroll 8
        for (int k = 0; k < 32; ++k) {
            ulonglong2 A0 = *(const ulonglong2*)(wsp + k * 32 + aw0);
            ulonglong2 A1 = *(const ulonglong2*)(wsp + k * 32 + aw1);
            float4 bv     = *(const float4*)    (hsp + k * 32 + hw);
            u64 b0 = pk2(bv.x), b1 = pk2(bv.y), b2 = pk2(bv.z), b3 = pk2(bv.w);
            ffma2(acc[0][0], A0.x, b0, acc[0][0]);
            ffma2(acc[0][1], A0.x, b1, acc[0][1]);
            ffma2(acc[0][2], A0.x, b2, acc[0][2]);
            ffma2(acc[0][3], A0.x, b3, acc[0][3]);
            ffma2(acc[1][0], A0.y, b0, acc[1][0]);
            ffma2(acc[1][1], A0.y, b1, acc[1][1]);
            ffma2(acc[1][2], A0.y, b2, acc[1][2]);
            ffma2(acc[1][3], A0.y, b3, acc[1][3]);
            ffma2(acc[2][0], A1.x, b0, acc[2][0]);
            ffma2(acc[2][1], A1.x, b1, acc[2][1]);
            ffma2(acc[2][2], A1.x, b2, acc[2][2]);
            ffma2(acc[2][3], A1.x, b3, acc[2][3]);
            ffma2(acc[3][0], A1.y, b0, acc[3][0]);
            ffma2(acc[3][1], A1.y, b1, acc[3][1]);
            ffma2(acc[3][2], A1.y, b2, acc[3][2]);
            ffma2(acc[3][3], A1.y, b3, acc[3][3]);
        }

        #pragma unroll
        for (int mp = 0; mp < 4; ++mp)
            #pragma unroll
            for (int n = 0; n < 4; ++n)
                Red[(gid * 16 + tm * 4 + mp) * 17 + (tn * 4 + n)] = acc[mp][n];
        __syncthreads();

        // ---- reduce 16 groups ----
        {
            int rp = tid >> 4, b = tid & 15;
            u64 s = Red[rp * 17 + b];
            #pragma unroll
            for (int g = 1; g < 16; ++g)
                fadd2(s, s, Red[(g * 16 + rp) * 17 + b]);
            float2 f = up2(s);
            Gs[(rp * 2    ) * 16 + b] = f.x;
            Gs[(rp * 2 + 1) * 16 + b] = f.y;
        }
        __syncthreads();

        // ---- LSTM cell update ----
        if (tid < 128) {
            const int j = jj, b = bbt;
            float zi = xq0 + Gs[(     j) * 16 + b];
            float zf = xq1 + Gs[( 8 + j) * 16 + b];
            float zg = xq2 + Gs[(16 + j) * 16 + b];
            float zo = xq3 + Gs[(24 + j) * 16 + b];
            float ig = sigfast(zi);
            float fg = sigfast(zf);
            float gg = tanhfast(zg);
            float og = sigfast(zo);
            float cn = fg * Cs[b * 8 + j] + ig * gg;
            Cs[b * 8 + j] = cn;
            float hn = og * tanhfast(cn);

            g_hT[(t + 1) & 1][(jb + j) * 32 + bb + b] = hn;
            out[((size_t)t * 32 + bb + b) * 512 + jb + j] = hn;

            if (t == T_STEPS - 1) {
                long long need = (long long)T_STEPS * BATCH * HID + 2LL * BATCH * HID;
                if (out_size >= need) {
                    size_t ob = (size_t)T_STEPS * BATCH * HID;
                    out[ob + (bb + b) * 512 + jb + j]               = hn;  // h_f
                    out[ob + BATCH * HID + (bb + b) * 512 + jb + j] = cn;  // c_f
                }
            }
        }

        // ---- grid barrier (single hot counter per batch-group) ----
        if (t < T_STEPS - 1) {
            __threadfence();
            __syncthreads();
            if (tid == 0) {
                atomicAdd(&g_bar2[bg][0], 1u);
                unsigned target = (unsigned)(t + 1) * 64u;
                while (*((volatile unsigned*)&g_bar2[bg][0]) < target) { }
            }
            __syncthreads();
        }
    }
}

// ============================================================================
extern "C" void kernel_launch(void* const* d_in, const int* in_sizes, int n_in,
                              void* d_out, int out_size)
{
    const float* seq = (const float*)d_in[0];
    const float* h0  = (const float*)d_in[1];
    const float* c0  = (const float*)d_in[2];
    const float* Wih = (const float*)d_in[3];
    const float* Whh = (const float*)d_in[4];
    const float* bih = (const float*)d_in[5];
    const float* bhh = (const float*)d_in[6];
    float* out = (float*)d_out;
    (void)in_sizes; (void)n_in;

    size_t smemA = (size_t)(2 * 4096 + 2 * 2048) * sizeof(float);   // 49152
    cudaFuncSetAttribute(xproj_kernel,
                         cudaFuncAttributeMaxDynamicSharedMemorySize, (int)smemA);
    dim3 gA(2048 / 64, (T_STEPS * BATCH) / 128);   // (32, 512)
    xproj_kernel<<<gA, 256, smemA>>>(seq, Wih, bih, bhh);

    reset_kernel<<<1, 32>>>();

    size_t smem = (size_t)(512 * 32 + 512 * 32 + 512) * sizeof(float)
                + (size_t)(16 * 16 * 17) * sizeof(u64)
                + (size_t)128 * sizeof(float);
    cudaFuncSetAttribute(lstm_rec_kernel,
                         cudaFuncAttributeMaxDynamicSharedMemorySize, (int)smem);
    lstm_rec_kernel<<<128, 256, smem>>>(h0, c0, Whh, out, (long long)out_size);
}